// round 7
// baseline (speedup 1.0000x reference)
#include <cuda_runtime.h>
#include <cuda_bf16.h>
#include <math.h>
#include <stdint.h>

#define N_MAX   100000
#define E_MAX   3300000
#define IN_CH   512
#define H1F     64      // heads1*ch1
#define OUT_CH  16

// ---------------- device scratch (no allocation allowed) ----------------
__device__ float g_h1  [(size_t)N_MAX * H1F];    // x@W1
__device__ float g_e1s [(size_t)N_MAX * 8];
__device__ float g_e1d [(size_t)N_MAX * 8];
__device__ float g_hact[(size_t)N_MAX * H1F];    // elu(layer1 out)
__device__ float g_h2  [(size_t)N_MAX * OUT_CH]; // hact@W2
__device__ float g_e2s [N_MAX];
__device__ float g_e2d [N_MAX];
__device__ int   g_deg [N_MAX];
__device__ int   g_off [N_MAX + 1];
__device__ int   g_cur [N_MAX];
__device__ int   g_csr [E_MAX];
__device__ int   g_bsum[128];

// ---------------- packed f32x2 helpers (base sm_100 feature) ----------------
__device__ __forceinline__ void fma_f32x2(unsigned long long& acc,
                                          unsigned long long a, unsigned long long b) {
    asm("fma.rn.f32x2 %0, %1, %2, %0;" : "+l"(acc) : "l"(a), "l"(b));
}
__device__ __forceinline__ unsigned long long pack_ff(float v) {
    unsigned long long r;
    asm("mov.b64 %0, {%1, %1};" : "=l"(r) : "f"(v));
    return r;
}
__device__ __forceinline__ void unpack_ff(unsigned long long p, float& lo, float& hi) {
    asm("mov.b64 {%0, %1}, %2;" : "=f"(lo), "=f"(hi) : "l"(p));
}
__device__ __forceinline__ uint32_t smem_u32(const void* p) {
    uint32_t a;
    asm("{ .reg .u64 t; cvta.to.shared.u64 t, %1; cvt.u32.u64 %0, t; }" : "=r"(a) : "l"(p));
    return a;
}
__device__ __forceinline__ void cpa16(uint32_t dst, const void* src) {
    asm volatile("cp.async.ca.shared.global [%0], [%1], 16;" :: "r"(dst), "l"(src));
}

// ---------------- CSR build ----------------
__global__ void k_zero(int N) {
    int i = blockIdx.x * blockDim.x + threadIdx.x;
    if (i < N) g_deg[i] = 0;
}

__global__ void k_deg(const int* __restrict__ ei, int E_orig, int E_tot) {
    int i = blockIdx.x * blockDim.x + threadIdx.x;
    if (i >= E_tot) return;
    int dst = (i < E_orig) ? ei[E_orig + i] : (i - E_orig);
    atomicAdd(&g_deg[dst], 1);
}

__global__ void k_scanA(int N) {      // grid: ceil(N/1024), block 1024
    __shared__ int s[1024];
    int tid = threadIdx.x;
    int i = blockIdx.x * 1024 + tid;
    int v = (i < N) ? g_deg[i] : 0;
    s[tid] = v;
    __syncthreads();
    for (int o = 1; o < 1024; o <<= 1) {
        int t = (tid >= o) ? s[tid - o] : 0;
        __syncthreads();
        s[tid] += t;
        __syncthreads();
    }
    if (i < N) g_off[i + 1] = s[tid];
    if (tid == 1023) g_bsum[blockIdx.x] = s[1023];
}

__global__ void k_scanB(int nb) {     // <<<1,1>>>
    int run = 0;
    for (int b = 0; b < nb; b++) {
        int t = g_bsum[b];
        g_bsum[b] = run;
        run += t;
    }
}

__global__ void k_scanC(int N) {
    int i = blockIdx.x * blockDim.x + threadIdx.x;
    if (i < N) g_off[i + 1] += g_bsum[i >> 10];
    if (i == 0) g_off[0] = 0;
}

__global__ void k_cursor(int N) {
    int i = blockIdx.x * blockDim.x + threadIdx.x;
    if (i < N) g_cur[i] = g_off[i];
}

__global__ void k_scatter(const int* __restrict__ ei, int E_orig, int E_tot) {
    int i = blockIdx.x * blockDim.x + threadIdx.x;
    if (i >= E_tot) return;
    int src, dst;
    if (i < E_orig) { src = ei[i]; dst = ei[E_orig + i]; }
    else            { src = i - E_orig; dst = src; }
    int p = atomicAdd(&g_cur[dst], 1);
    g_csr[p] = src;
}

// ---------------- GEMM1: h1 = x @ W1  (+ e1_src/e1_dst) ----------------
// tile: 128 nodes x 64 cols, K-chunks of 32. Thread: 4 nodes x 8 cols.
// Double-buffered: xs via register-staged LDG (odd stride -> no cp.async),
// ws via cp.async (warp-broadcast reads -> stride 64 is fine). One barrier
// per chunk; no global load on the critical path.
#define XS_FLOATS 4224              // 128 * 33
#define WS_FLOATS 2048              // 32 * 64
#define G1_SMEM   ((2 * XS_FLOATS + 2 * WS_FLOATS) * 4)   // 50176 B

__global__ __launch_bounds__(256, 3) void k_gemm1(
    const float* __restrict__ x, const float* __restrict__ W1,
    const float* __restrict__ a1s, const float* __restrict__ a1d, int N)
{
    extern __shared__ float sm[];
    float* xsb0 = sm;
    float* xsb1 = sm + XS_FLOATS;
    float* wsb0 = sm + 2 * XS_FLOATS;

    int t  = threadIdx.x;
    int ng = t & 31;     // node lane (nodes ng, ng+32, ng+64, ng+96)
    int cg = t >> 5;     // head index 0..7 (cols cg*8 .. cg*8+7)
    int n0 = blockIdx.x * 128;

    // per-thread x staging geometry (float offsets within one xs buffer)
    const float* xrow[4];
    int  xoff[4];
    bool xok[4];
#pragma unroll
    for (int r = 0; r < 4; r++) {
        int f4   = t + r * 256;
        int node = f4 >> 3;
        int kk4  = f4 & 7;
        int gn   = n0 + node;
        xok[r]  = (gn < N);
        xrow[r] = &x[(size_t)(xok[r] ? gn : 0) * IN_CH + kk4 * 4];
        xoff[r] = node * 33 + kk4 * 4;
    }
    // ws geometry: 2 float4 per thread; W1 index = k0*64 + woff
    int woff[2];
#pragma unroll
    for (int r = 0; r < 2; r++) {
        int f4 = t + r * 256;
        woff[r] = (f4 >> 4) * 64 + (f4 & 15) * 4;
    }
    const uint32_t ws0_u = smem_u32(wsb0);

    unsigned long long acc2[4][4];
#pragma unroll
    for (int j = 0; j < 4; j++)
#pragma unroll
        for (int c = 0; c < 4; c++) acc2[j][c] = 0ULL;

    float4 xstg[4];
    // ---- prologue: chunk0 x+w, chunk1 x+w in flight
#pragma unroll
    for (int r = 0; r < 4; r++) {
        float4 v = make_float4(0.f, 0.f, 0.f, 0.f);
        if (xok[r]) v = *reinterpret_cast<const float4*>(xrow[r]);
        xstg[r] = v;
    }
#pragma unroll
    for (int r = 0; r < 2; r++) cpa16(ws0_u + woff[r] * 4, W1 + woff[r]);
    asm volatile("cp.async.commit_group;");
#pragma unroll
    for (int r = 0; r < 4; r++) {
        float* p = xsb0 + xoff[r];
        p[0] = xstg[r].x; p[1] = xstg[r].y; p[2] = xstg[r].z; p[3] = xstg[r].w;
    }
#pragma unroll
    for (int r = 0; r < 4; r++) {
        float4 v = make_float4(0.f, 0.f, 0.f, 0.f);
        if (xok[r]) v = *reinterpret_cast<const float4*>(xrow[r] + 32);
        xstg[r] = v;
    }
#pragma unroll
    for (int r = 0; r < 2; r++)
        cpa16(ws0_u + WS_FLOATS * 4 + woff[r] * 4, W1 + 32 * 64 + woff[r]);
    asm volatile("cp.async.commit_group;");
    asm volatile("cp.async.wait_group 1;");   // ws chunk0 done
    __syncthreads();

    for (int ch = 0; ch < 16; ch++) {
        int cur = ch & 1;
        const float* xs = cur ? xsb1 : xsb0;
        const float* ws = wsb0 + cur * WS_FLOATS;
#pragma unroll
        for (int k = 0; k < 32; k++) {
            ulonglong2 w01 = *reinterpret_cast<const ulonglong2*>(&ws[k * 64 + cg * 8]);
            ulonglong2 w23 = *reinterpret_cast<const ulonglong2*>(&ws[k * 64 + cg * 8 + 4]);
#pragma unroll
            for (int j = 0; j < 4; j++) {
                unsigned long long xp = pack_ff(xs[(ng + 32 * j) * 33 + k]);
                fma_f32x2(acc2[j][0], xp, w01.x);
                fma_f32x2(acc2[j][1], xp, w01.y);
                fma_f32x2(acc2[j][2], xp, w23.x);
                fma_f32x2(acc2[j][3], xp, w23.y);
            }
        }
        if (ch < 15) {
            float* xn = cur ? xsb0 : xsb1;
#pragma unroll
            for (int r = 0; r < 4; r++) {
                float* p = xn + xoff[r];
                p[0] = xstg[r].x; p[1] = xstg[r].y; p[2] = xstg[r].z; p[3] = xstg[r].w;
            }
            // ws[ch+1] was committed one full compute phase ago -> no stall
            asm volatile("cp.async.wait_group 0;");
            __syncthreads();
            if (ch < 14) {
                int k2 = (ch + 2) * 32;
#pragma unroll
                for (int r = 0; r < 4; r++) {
                    float4 v = make_float4(0.f, 0.f, 0.f, 0.f);
                    if (xok[r]) v = *reinterpret_cast<const float4*>(xrow[r] + k2);
                    xstg[r] = v;
                }
#pragma unroll
                for (int r = 0; r < 2; r++)
                    cpa16(ws0_u + cur * (WS_FLOATS * 4) + woff[r] * 4,
                          W1 + (size_t)k2 * 64 + woff[r]);
                asm volatile("cp.async.commit_group;");
            }
        }
    }

    float as[8], ad[8];
#pragma unroll
    for (int c = 0; c < 8; c++) { as[c] = a1s[cg * 8 + c]; ad[c] = a1d[cg * 8 + c]; }

#pragma unroll
    for (int j = 0; j < 4; j++) {
        int node = n0 + ng + 32 * j;
        if (node >= N) continue;
        float acc[8];
#pragma unroll
        for (int c = 0; c < 4; c++) unpack_ff(acc2[j][c], acc[2 * c], acc[2 * c + 1]);
        float es = 0.f, ed = 0.f;
#pragma unroll
        for (int c = 0; c < 8; c++) {
            es = fmaf(acc[c], as[c], es);
            ed = fmaf(acc[c], ad[c], ed);
        }
        *reinterpret_cast<float4*>(&g_h1[(size_t)node * H1F + cg * 8]) =
            make_float4(acc[0], acc[1], acc[2], acc[3]);
        *reinterpret_cast<float4*>(&g_h1[(size_t)node * H1F + cg * 8 + 4]) =
            make_float4(acc[4], acc[5], acc[6], acc[7]);
        g_e1s[node * 8 + cg] = es;
        g_e1d[node * 8 + cg] = ed;
    }
}

// ---------------- layer-1 edge aggregation (warp per dst, unroll x2) ----------
// No segment-max needed: logits are O(1), exp() is safe, and
// alpha = exp(l)/sum exp(l) is identical to the max-subtracted form.
__global__ void k_edge1(const float* __restrict__ b1, int N) {
    int w = (blockIdx.x * blockDim.x + threadIdx.x) >> 5;
    if (w >= N) return;
    int lane = threadIdx.x & 31;
    int h0 = lane >> 3;              // feature f0=lane -> head lane/8
    const float ed0 = g_e1d[w * 8 + h0];
    const float ed1 = g_e1d[w * 8 + 4 + h0];   // f1 = lane+32 -> head 4+lane/8
    int beg = g_off[w], end = g_off[w + 1];
    float acc0 = 0.f, acc1 = 0.f, dn0 = 0.f, dn1 = 0.f;
    int i = beg;
    for (; i + 2 <= end; i += 2) {
        int sA = __ldg(&g_csr[i]);
        int sB = __ldg(&g_csr[i + 1]);
        float tA0 = __ldg(&g_e1s[sA * 8 + h0]) + ed0;
        float tA1 = __ldg(&g_e1s[sA * 8 + 4 + h0]) + ed1;
        float tB0 = __ldg(&g_e1s[sB * 8 + h0]) + ed0;
        float tB1 = __ldg(&g_e1s[sB * 8 + 4 + h0]) + ed1;
        float hA0 = __ldg(&g_h1[(size_t)sA * H1F + lane]);
        float hA1 = __ldg(&g_h1[(size_t)sA * H1F + 32 + lane]);
        float hB0 = __ldg(&g_h1[(size_t)sB * H1F + lane]);
        float hB1 = __ldg(&g_h1[(size_t)sB * H1F + 32 + lane]);
        tA0 = tA0 > 0.f ? tA0 : 0.2f * tA0;
        tA1 = tA1 > 0.f ? tA1 : 0.2f * tA1;
        tB0 = tB0 > 0.f ? tB0 : 0.2f * tB0;
        tB1 = tB1 > 0.f ? tB1 : 0.2f * tB1;
        float wA0 = __expf(tA0), wA1 = __expf(tA1);
        float wB0 = __expf(tB0), wB1 = __expf(tB1);
        acc0 = fmaf(wA0, hA0, acc0); dn0 += wA0;
        acc1 = fmaf(wA1, hA1, acc1); dn1 += wA1;
        acc0 = fmaf(wB0, hB0, acc0); dn0 += wB0;
        acc1 = fmaf(wB1, hB1, acc1); dn1 += wB1;
    }
    if (i < end) {
        int s = __ldg(&g_csr[i]);
        float t0 = __ldg(&g_e1s[s * 8 + h0]) + ed0;
        float t1 = __ldg(&g_e1s[s * 8 + 4 + h0]) + ed1;
        t0 = t0 > 0.f ? t0 : 0.2f * t0;
        t1 = t1 > 0.f ? t1 : 0.2f * t1;
        float w0 = __expf(t0);
        float w1 = __expf(t1);
        acc0 = fmaf(w0, __ldg(&g_h1[(size_t)s * H1F + lane]), acc0);
        acc1 = fmaf(w1, __ldg(&g_h1[(size_t)s * H1F + 32 + lane]), acc1);
        dn0 += w0; dn1 += w1;
    }
    float v0 = acc0 / dn0 + b1[lane];
    float v1 = acc1 / dn1 + b1[lane + 32];
    v0 = v0 > 0.f ? v0 : (__expf(v0) - 1.f);   // ELU
    v1 = v1 > 0.f ? v1 : (__expf(v1) - 1.f);
    g_hact[(size_t)w * H1F + lane]      = v0;
    g_hact[(size_t)w * H1F + 32 + lane] = v1;
}

// ---------------- GEMM2: h2 = hact @ W2 (+ e2_src/e2_dst), packed f32x2 -------
__global__ __launch_bounds__(256) void k_gemm2(
    const float* __restrict__ W2, const float* __restrict__ a2s,
    const float* __restrict__ a2d, int N)
{
    __shared__ float hs[64 * 65];
    __shared__ float ws[64 * 16];
    __shared__ float h2s[64 * 17];
    int t  = threadIdx.x;
    int n0 = blockIdx.x * 64;
#pragma unroll
    for (int r = 0; r < 4; r++) {
        int f4   = t + r * 256;
        int node = f4 >> 4;
        int k4   = f4 & 15;
        int gn   = n0 + node;
        float4 v = make_float4(0.f, 0.f, 0.f, 0.f);
        if (gn < N)
            v = *reinterpret_cast<const float4*>(&g_hact[(size_t)gn * H1F + k4 * 4]);
        float* p = &hs[node * 65 + k4 * 4];
        p[0] = v.x; p[1] = v.y; p[2] = v.z; p[3] = v.w;
    }
    {   // W2: 64x16 = 256 float4
        int k  = t >> 2;
        int c4 = t & 3;
        *reinterpret_cast<float4*>(&ws[k * 16 + c4 * 4]) =
            *reinterpret_cast<const float4*>(&W2[k * 16 + c4 * 4]);
    }
    __syncthreads();

    int j  = t >> 2;          // node within tile
    int c0 = (t & 3) * 4;     // output col group
    unsigned long long acc2[2] = {0ULL, 0ULL};
#pragma unroll
    for (int k = 0; k < 64; k++) {
        unsigned long long xp = pack_ff(hs[j * 65 + k]);
        ulonglong2 wv = *reinterpret_cast<const ulonglong2*>(&ws[k * 16 + c0]);
        fma_f32x2(acc2[0], xp, wv.x);
        fma_f32x2(acc2[1], xp, wv.y);
    }
    float acc[4];
    unpack_ff(acc2[0], acc[0], acc[1]);
    unpack_ff(acc2[1], acc[2], acc[3]);
    int gn = n0 + j;
    if (gn < N)
        *reinterpret_cast<float4*>(&g_h2[(size_t)gn * OUT_CH + c0]) =
            make_float4(acc[0], acc[1], acc[2], acc[3]);
#pragma unroll
    for (int c = 0; c < 4; c++) h2s[j * 17 + c0 + c] = acc[c];
    __syncthreads();
    if (t < 64) {
        int gn2 = n0 + t;
        if (gn2 < N) {
            float es = 0.f, ed = 0.f;
#pragma unroll
            for (int c = 0; c < OUT_CH; c++) {
                float v = h2s[t * 17 + c];
                es = fmaf(v, a2s[c], es);
                ed = fmaf(v, a2d[c], ed);
            }
            g_e2s[gn2] = es;
            g_e2d[gn2] = ed;
        }
    }
}

// ---------------- layer-2 edge aggregation + fused log_softmax ----------------
__global__ void k_edge2(const float* __restrict__ b2, float* __restrict__ out, int N) {
    int w = (blockIdx.x * blockDim.x + threadIdx.x) >> 5;
    if (w >= N) return;
    int lane = threadIdx.x & 31;
    int c = lane & 15;
    int g = lane >> 4;        // two edges per iteration (half-warp each)
    float ed = g_e2d[w];
    int beg = g_off[w], end = g_off[w + 1];
    float acc = 0.f, dn = 0.f;
    for (int i = beg + g; i < end; i += 2) {
        int s = __ldg(&g_csr[i]);
        float t = __ldg(&g_e2s[s]) + ed;
        t = t > 0.f ? t : 0.2f * t;
        float wt = __expf(t);
        acc = fmaf(wt, __ldg(&g_h2[(size_t)s * OUT_CH + c]), acc);
        dn += wt;
    }
    acc += __shfl_xor_sync(0xffffffffu, acc, 16);
    dn  += __shfl_xor_sync(0xffffffffu, dn, 16);
    float v = acc / dn + b2[c];
    // log_softmax over the 16 channels (both half-warps hold identical copies)
    float m = v;
#pragma unroll
    for (int o = 8; o; o >>= 1) m = fmaxf(m, __shfl_xor_sync(0xffffffffu, m, o));
    float S = __expf(v - m);
#pragma unroll
    for (int o = 8; o; o >>= 1) S += __shfl_xor_sync(0xffffffffu, S, o);
    if (lane < 16) out[(size_t)w * OUT_CH + c] = (v - m) - __logf(S);
}

// ---------------- launch ----------------
extern "C" void kernel_launch(void* const* d_in, const int* in_sizes, int n_in,
                              void* d_out, int out_size)
{
    const float* x   = (const float*)d_in[0];
    const int*   ei  = (const int*)  d_in[1];
    const float* W1  = (const float*)d_in[2];
    const float* a1s = (const float*)d_in[3];
    const float* a1d = (const float*)d_in[4];
    const float* b1  = (const float*)d_in[5];
    const float* W2  = (const float*)d_in[6];
    const float* a2s = (const float*)d_in[7];
    const float* a2d = (const float*)d_in[8];
    const float* b2  = (const float*)d_in[9];
    float* out = (float*)d_out;

    int N      = in_sizes[0] / IN_CH;     // 100000
    int E_orig = in_sizes[1] / 2;         // 3200000
    int E_tot  = E_orig + N;

    cudaFuncSetAttribute(k_gemm1, cudaFuncAttributeMaxDynamicSharedMemorySize, G1_SMEM);

    // gemm1 kept at launch index 3 so the fixed ncu skip-count profiles it.
    k_zero   <<<(N + 255) / 256, 256>>>(N);
    k_deg    <<<(E_tot + 255) / 256, 256>>>(ei, E_orig, E_tot);
    k_scanA  <<<(N + 1023) / 1024, 1024>>>(N);
    k_gemm1  <<<(N + 127) / 128, 256, G1_SMEM>>>(x, W1, a1s, a1d, N);
    k_scanB  <<<1, 1>>>((N + 1023) / 1024);
    k_scanC  <<<(N + 255) / 256, 256>>>(N);
    k_cursor <<<(N + 255) / 256, 256>>>(N);
    k_scatter<<<(E_tot + 255) / 256, 256>>>(ei, E_orig, E_tot);

    // layer 1 aggregation
    k_edge1<<<(N * 32 + 255) / 256, 256>>>(b1, N);

    // layer 2 + fused log_softmax
    k_gemm2<<<(N + 63) / 64, 256>>>(W2, a2s, a2d, N);
    k_edge2<<<(N * 32 + 255) / 256, 256>>>(b2, out, N);
}

// round 8
// speedup vs baseline: 1.0836x; 1.0836x over previous
#include <cuda_runtime.h>
#include <cuda_bf16.h>
#include <math.h>
#include <stdint.h>

#define N_MAX   100000
#define E_MAX   3300000
#define IN_CH   512
#define H1F     64      // heads1*ch1
#define OUT_CH  16
#define KSTEPS  32      // 512 / 16

// ---------------- device scratch (no allocation allowed) ----------------
__device__ float g_h1  [(size_t)N_MAX * H1F];    // x@W1
__device__ float g_e1s [(size_t)N_MAX * 8];
__device__ float g_e1d [(size_t)N_MAX * 8];
__device__ float g_hact[(size_t)N_MAX * H1F];    // elu(layer1 out)
__device__ float g_h2  [(size_t)N_MAX * OUT_CH]; // hact@W2
__device__ float g_e2s [N_MAX];
__device__ float g_e2d [N_MAX];
__device__ int   g_deg [N_MAX];
__device__ int   g_off [N_MAX + 1];
__device__ int   g_cur [N_MAX];
__device__ int   g_csr [E_MAX];
__device__ int   g_bsum[128];
// W1 pre-packed into mma B-fragment layout (bf16 hi / lo), [ks][nfp][lane]
__device__ uint4 g_wp_h[KSTEPS * 4 * 32];
__device__ uint4 g_wp_l[KSTEPS * 4 * 32];

// ---------------- bf16 split helpers ----------------
// hi = truncate-to-bf16 (top 16 bits); pack pair {f0 -> low half, f1 -> high half}
__device__ __forceinline__ uint32_t hi_pack(float f0, float f1) {
    return __byte_perm(__float_as_uint(f0), __float_as_uint(f1), 0x7632);
}
__device__ __forceinline__ uint32_t lo_pack(float f0, float f1) {
    float l0 = f0 - __uint_as_float(__float_as_uint(f0) & 0xffff0000u);
    float l1 = f1 - __uint_as_float(__float_as_uint(f1) & 0xffff0000u);
    uint32_t r;
    asm("cvt.rn.bf16x2.f32 %0, %1, %2;" : "=r"(r) : "f"(l1), "f"(l0));  // first src -> high half
    return r;
}
__device__ __forceinline__ void mma_bf16(float* d,
                                         uint32_t a0, uint32_t a1, uint32_t a2, uint32_t a3,
                                         uint32_t b0, uint32_t b1) {
    asm("mma.sync.aligned.m16n8k16.row.col.f32.bf16.bf16.f32 "
        "{%0,%1,%2,%3}, {%4,%5,%6,%7}, {%8,%9}, {%0,%1,%2,%3};"
        : "+f"(d[0]), "+f"(d[1]), "+f"(d[2]), "+f"(d[3])
        : "r"(a0), "r"(a1), "r"(a2), "r"(a3), "r"(b0), "r"(b1));
}

// ---------------- packed f32x2 helpers (for gemm2) ----------------
__device__ __forceinline__ void fma_f32x2(unsigned long long& acc,
                                          unsigned long long a, unsigned long long b) {
    asm("fma.rn.f32x2 %0, %1, %2, %0;" : "+l"(acc) : "l"(a), "l"(b));
}
__device__ __forceinline__ unsigned long long pack_ff(float v) {
    unsigned long long r;
    asm("mov.b64 %0, {%1, %1};" : "=l"(r) : "f"(v));
    return r;
}
__device__ __forceinline__ void unpack_ff(unsigned long long p, float& lo, float& hi) {
    asm("mov.b64 {%0, %1}, %2;" : "=f"(lo), "=f"(hi) : "l"(p));
}

// ---------------- CSR build ----------------
__global__ void k_zero(int N) {
    int i = blockIdx.x * blockDim.x + threadIdx.x;
    if (i < N) g_deg[i] = 0;
}

__global__ void k_deg(const int* __restrict__ ei, int E_orig, int E_tot) {
    int i = blockIdx.x * blockDim.x + threadIdx.x;
    if (i >= E_tot) return;
    int dst = (i < E_orig) ? ei[E_orig + i] : (i - E_orig);
    atomicAdd(&g_deg[dst], 1);
}

__global__ void k_scanA(int N) {      // grid: ceil(N/1024), block 1024
    __shared__ int s[1024];
    int tid = threadIdx.x;
    int i = blockIdx.x * 1024 + tid;
    int v = (i < N) ? g_deg[i] : 0;
    s[tid] = v;
    __syncthreads();
    for (int o = 1; o < 1024; o <<= 1) {
        int t = (tid >= o) ? s[tid - o] : 0;
        __syncthreads();
        s[tid] += t;
        __syncthreads();
    }
    if (i < N) g_off[i + 1] = s[tid];
    if (tid == 1023) g_bsum[blockIdx.x] = s[1023];
}

__global__ void k_scanB(int nb) {     // <<<1,1>>>
    int run = 0;
    for (int b = 0; b < nb; b++) {
        int t = g_bsum[b];
        g_bsum[b] = run;
        run += t;
    }
}

__global__ void k_scanC(int N) {
    int i = blockIdx.x * blockDim.x + threadIdx.x;
    if (i < N) g_off[i + 1] += g_bsum[i >> 10];
    if (i == 0) g_off[0] = 0;
}

__global__ void k_cursor(int N) {
    int i = blockIdx.x * blockDim.x + threadIdx.x;
    if (i < N) g_cur[i] = g_off[i];
}

__global__ void k_scatter(const int* __restrict__ ei, int E_orig, int E_tot) {
    int i = blockIdx.x * blockDim.x + threadIdx.x;
    if (i >= E_tot) return;
    int src, dst;
    if (i < E_orig) { src = ei[i]; dst = ei[E_orig + i]; }
    else            { src = i - E_orig; dst = src; }
    int p = atomicAdd(&g_cur[dst], 1);
    g_csr[p] = src;
}

// ---------------- W1 pre-pack into B-fragment layout ----------------
// B frag (m16n8k16, col): lane l (g=l>>2, t=l&3): b0={B[2t][g],B[2t+1][g]},
// b1={B[2t+8][g],B[2t+9][g]}. uint4 per (ks,nfp,lane) = {nf0.b0, nf0.b1, nf1.b0, nf1.b1}.
__global__ void k_wsplit(const float* __restrict__ W1) {
    int i = blockIdx.x * blockDim.x + threadIdx.x;   // 0 .. 4095
    if (i >= KSTEPS * 4 * 32) return;
    int ks  = i >> 7;
    int nfp = (i >> 5) & 3;
    int l   = i & 31;
    int g = l >> 2, t = l & 3;
    uint32_t h[4], lo[4];
#pragma unroll
    for (int j = 0; j < 4; j++) {
        int nf  = nfp * 2 + (j >> 1);
        int reg = j & 1;
        int k0  = ks * 16 + 2 * t + reg * 8;
        int col = nf * 8 + g;
        float w0 = W1[k0 * 64 + col];
        float w1 = W1[(k0 + 1) * 64 + col];
        h[j]  = hi_pack(w0, w1);
        lo[j] = lo_pack(w0, w1);
    }
    g_wp_h[i] = make_uint4(h[0], h[1], h[2], h[3]);
    g_wp_l[i] = make_uint4(lo[0], lo[1], lo[2], lo[3]);
}

// ---------------- GEMM1 via mma.sync bf16 hi/lo split ----------------
// Warp = 16 rows x 64 cols. A from global fp32 (converted in regs), B from
// pre-packed g_wp_* (L1-hot). No smem, no barriers.
__global__ __launch_bounds__(256) void k_gemm1(
    const float* __restrict__ x,
    const float* __restrict__ a1s, const float* __restrict__ a1d, int N)
{
    int t    = threadIdx.x;
    int wid  = t >> 5;
    int lane = t & 31;
    int g = lane >> 2, q = lane & 3;
    int m0 = blockIdx.x * 128 + wid * 16;
    int r0 = m0 + g;          // rows g and g+8 of the warp tile
    int r1 = m0 + g + 8;
    const float* xr0 = x + (size_t)(r0 < N ? r0 : 0) * IN_CH + 2 * q;
    const float* xr1 = x + (size_t)(r1 < N ? r1 : 0) * IN_CH + 2 * q;

    float acc[8][4];
#pragma unroll
    for (int h = 0; h < 8; h++)
#pragma unroll
        for (int c = 0; c < 4; c++) acc[h][c] = 0.f;

#pragma unroll 4
    for (int ks = 0; ks < KSTEPS; ks++) {
        float2 f0 = *reinterpret_cast<const float2*>(xr0 + ks * 16);
        float2 f1 = *reinterpret_cast<const float2*>(xr1 + ks * 16);
        float2 f2 = *reinterpret_cast<const float2*>(xr0 + ks * 16 + 8);
        float2 f3 = *reinterpret_cast<const float2*>(xr1 + ks * 16 + 8);
        uint32_t ah0 = hi_pack(f0.x, f0.y), ah1 = hi_pack(f1.x, f1.y);
        uint32_t ah2 = hi_pack(f2.x, f2.y), ah3 = hi_pack(f3.x, f3.y);
        uint32_t al0 = lo_pack(f0.x, f0.y), al1 = lo_pack(f1.x, f1.y);
        uint32_t al2 = lo_pack(f2.x, f2.y), al3 = lo_pack(f3.x, f3.y);

        const uint4* wph = &g_wp_h[ks * 128 + lane];
        const uint4* wpl = &g_wp_l[ks * 128 + lane];
#pragma unroll
        for (int nfp = 0; nfp < 4; nfp++) {
            uint4 wh = wph[nfp * 32];
            uint4 wl = wpl[nfp * 32];
            // nf = 2*nfp : (wh.x, wh.y)
            mma_bf16(acc[2 * nfp],     ah0, ah1, ah2, ah3, wh.x, wh.y);
            mma_bf16(acc[2 * nfp],     ah0, ah1, ah2, ah3, wl.x, wl.y);
            mma_bf16(acc[2 * nfp],     al0, al1, al2, al3, wh.x, wh.y);
            // nf = 2*nfp+1 : (wh.z, wh.w)
            mma_bf16(acc[2 * nfp + 1], ah0, ah1, ah2, ah3, wh.z, wh.w);
            mma_bf16(acc[2 * nfp + 1], ah0, ah1, ah2, ah3, wl.z, wl.w);
            mma_bf16(acc[2 * nfp + 1], al0, al1, al2, al3, wh.z, wh.w);
        }
    }

    // epilogue: store h1, compute e1s/e1d per head via quad reduction
    bool ok0 = (r0 < N), ok1 = (r1 < N);
#pragma unroll
    for (int h = 0; h < 8; h++) {
        if (ok0)
            *reinterpret_cast<float2*>(&g_h1[(size_t)r0 * H1F + h * 8 + 2 * q]) =
                make_float2(acc[h][0], acc[h][1]);
        if (ok1)
            *reinterpret_cast<float2*>(&g_h1[(size_t)r1 * H1F + h * 8 + 2 * q]) =
                make_float2(acc[h][2], acc[h][3]);
        float2 s = *reinterpret_cast<const float2*>(&a1s[h * 8 + 2 * q]);
        float2 d = *reinterpret_cast<const float2*>(&a1d[h * 8 + 2 * q]);
        float es0 = acc[h][0] * s.x + acc[h][1] * s.y;
        float ed0 = acc[h][0] * d.x + acc[h][1] * d.y;
        float es1 = acc[h][2] * s.x + acc[h][3] * s.y;
        float ed1 = acc[h][2] * d.x + acc[h][3] * d.y;
        es0 += __shfl_xor_sync(0xffffffffu, es0, 1);
        es0 += __shfl_xor_sync(0xffffffffu, es0, 2);
        ed0 += __shfl_xor_sync(0xffffffffu, ed0, 1);
        ed0 += __shfl_xor_sync(0xffffffffu, ed0, 2);
        es1 += __shfl_xor_sync(0xffffffffu, es1, 1);
        es1 += __shfl_xor_sync(0xffffffffu, es1, 2);
        ed1 += __shfl_xor_sync(0xffffffffu, ed1, 1);
        ed1 += __shfl_xor_sync(0xffffffffu, ed1, 2);
        if (q == 0) {
            if (ok0) { g_e1s[r0 * 8 + h] = es0; g_e1d[r0 * 8 + h] = ed0; }
            if (ok1) { g_e1s[r1 * 8 + h] = es1; g_e1d[r1 * 8 + h] = ed1; }
        }
    }
}

// ---------------- layer-1 edge aggregation (warp per dst, unroll x2) ----------
// No segment-max needed: logits are O(1), exp() is safe, and
// alpha = exp(l)/sum exp(l) is identical to the max-subtracted form.
__global__ void k_edge1(const float* __restrict__ b1, int N) {
    int w = (blockIdx.x * blockDim.x + threadIdx.x) >> 5;
    if (w >= N) return;
    int lane = threadIdx.x & 31;
    int h0 = lane >> 3;              // feature f0=lane -> head lane/8
    const float ed0 = g_e1d[w * 8 + h0];
    const float ed1 = g_e1d[w * 8 + 4 + h0];   // f1 = lane+32 -> head 4+lane/8
    int beg = g_off[w], end = g_off[w + 1];
    float acc0 = 0.f, acc1 = 0.f, dn0 = 0.f, dn1 = 0.f;
    int i = beg;
    for (; i + 2 <= end; i += 2) {
        int sA = __ldg(&g_csr[i]);
        int sB = __ldg(&g_csr[i + 1]);
        float tA0 = __ldg(&g_e1s[sA * 8 + h0]) + ed0;
        float tA1 = __ldg(&g_e1s[sA * 8 + 4 + h0]) + ed1;
        float tB0 = __ldg(&g_e1s[sB * 8 + h0]) + ed0;
        float tB1 = __ldg(&g_e1s[sB * 8 + 4 + h0]) + ed1;
        float hA0 = __ldg(&g_h1[(size_t)sA * H1F + lane]);
        float hA1 = __ldg(&g_h1[(size_t)sA * H1F + 32 + lane]);
        float hB0 = __ldg(&g_h1[(size_t)sB * H1F + lane]);
        float hB1 = __ldg(&g_h1[(size_t)sB * H1F + 32 + lane]);
        tA0 = tA0 > 0.f ? tA0 : 0.2f * tA0;
        tA1 = tA1 > 0.f ? tA1 : 0.2f * tA1;
        tB0 = tB0 > 0.f ? tB0 : 0.2f * tB0;
        tB1 = tB1 > 0.f ? tB1 : 0.2f * tB1;
        float wA0 = __expf(tA0), wA1 = __expf(tA1);
        float wB0 = __expf(tB0), wB1 = __expf(tB1);
        acc0 = fmaf(wA0, hA0, acc0); dn0 += wA0;
        acc1 = fmaf(wA1, hA1, acc1); dn1 += wA1;
        acc0 = fmaf(wB0, hB0, acc0); dn0 += wB0;
        acc1 = fmaf(wB1, hB1, acc1); dn1 += wB1;
    }
    if (i < end) {
        int s = __ldg(&g_csr[i]);
        float t0 = __ldg(&g_e1s[s * 8 + h0]) + ed0;
        float t1 = __ldg(&g_e1s[s * 8 + 4 + h0]) + ed1;
        t0 = t0 > 0.f ? t0 : 0.2f * t0;
        t1 = t1 > 0.f ? t1 : 0.2f * t1;
        float w0 = __expf(t0);
        float w1 = __expf(t1);
        acc0 = fmaf(w0, __ldg(&g_h1[(size_t)s * H1F + lane]), acc0);
        acc1 = fmaf(w1, __ldg(&g_h1[(size_t)s * H1F + 32 + lane]), acc1);
        dn0 += w0; dn1 += w1;
    }
    float v0 = acc0 / dn0 + b1[lane];
    float v1 = acc1 / dn1 + b1[lane + 32];
    v0 = v0 > 0.f ? v0 : (__expf(v0) - 1.f);   // ELU
    v1 = v1 > 0.f ? v1 : (__expf(v1) - 1.f);
    g_hact[(size_t)w * H1F + lane]      = v0;
    g_hact[(size_t)w * H1F + 32 + lane] = v1;
}

// ---------------- GEMM2: h2 = hact @ W2 (+ e2_src/e2_dst), packed f32x2 -------
__global__ __launch_bounds__(256) void k_gemm2(
    const float* __restrict__ W2, const float* __restrict__ a2s,
    const float* __restrict__ a2d, int N)
{
    __shared__ float hs[64 * 65];
    __shared__ float ws[64 * 16];
    __shared__ float h2s[64 * 17];
    int t  = threadIdx.x;
    int n0 = blockIdx.x * 64;
#pragma unroll
    for (int r = 0; r < 4; r++) {
        int f4   = t + r * 256;
        int node = f4 >> 4;
        int k4   = f4 & 15;
        int gn   = n0 + node;
        float4 v = make_float4(0.f, 0.f, 0.f, 0.f);
        if (gn < N)
            v = *reinterpret_cast<const float4*>(&g_hact[(size_t)gn * H1F + k4 * 4]);
        float* p = &hs[node * 65 + k4 * 4];
        p[0] = v.x; p[1] = v.y; p[2] = v.z; p[3] = v.w;
    }
    {   // W2: 64x16 = 256 float4
        int k  = t >> 2;
        int c4 = t & 3;
        *reinterpret_cast<float4*>(&ws[k * 16 + c4 * 4]) =
            *reinterpret_cast<const float4*>(&W2[k * 16 + c4 * 4]);
    }
    __syncthreads();

    int j  = t >> 2;          // node within tile
    int c0 = (t & 3) * 4;     // output col group
    unsigned long long acc2[2] = {0ULL, 0ULL};
#pragma unroll
    for (int k = 0; k < 64; k++) {
        unsigned long long xp = pack_ff(hs[j * 65 + k]);
        ulonglong2 wv = *reinterpret_cast<const ulonglong2*>(&ws[k * 16 + c0]);
        fma_f32x2(acc2[0], xp, wv.x);
        fma_f32x2(acc2[1], xp, wv.y);
    }
    float acc[4];
    unpack_ff(acc2[0], acc[0], acc[1]);
    unpack_ff(acc2[1], acc[2], acc[3]);
    int gn = n0 + j;
    if (gn < N)
        *reinterpret_cast<float4*>(&g_h2[(size_t)gn * OUT_CH + c0]) =
            make_float4(acc[0], acc[1], acc[2], acc[3]);
#pragma unroll
    for (int c = 0; c < 4; c++) h2s[j * 17 + c0 + c] = acc[c];
    __syncthreads();
    if (t < 64) {
        int gn2 = n0 + t;
        if (gn2 < N) {
            float es = 0.f, ed = 0.f;
#pragma unroll
            for (int c = 0; c < OUT_CH; c++) {
                float v = h2s[t * 17 + c];
                es = fmaf(v, a2s[c], es);
                ed = fmaf(v, a2d[c], ed);
            }
            g_e2s[gn2] = es;
            g_e2d[gn2] = ed;
        }
    }
}

// ---------------- layer-2 edge aggregation + fused log_softmax ----------------
__global__ void k_edge2(const float* __restrict__ b2, float* __restrict__ out, int N) {
    int w = (blockIdx.x * blockDim.x + threadIdx.x) >> 5;
    if (w >= N) return;
    int lane = threadIdx.x & 31;
    int c = lane & 15;
    int g = lane >> 4;        // two edges per iteration (half-warp each)
    float ed = g_e2d[w];
    int beg = g_off[w], end = g_off[w + 1];
    float acc = 0.f, dn = 0.f;
    for (int i = beg + g; i < end; i += 2) {
        int s = __ldg(&g_csr[i]);
        float t = __ldg(&g_e2s[s]) + ed;
        t = t > 0.f ? t : 0.2f * t;
        float wt = __expf(t);
        acc = fmaf(wt, __ldg(&g_h2[(size_t)s * OUT_CH + c]), acc);
        dn += wt;
    }
    acc += __shfl_xor_sync(0xffffffffu, acc, 16);
    dn  += __shfl_xor_sync(0xffffffffu, dn, 16);
    float v = acc / dn + b2[c];
    // log_softmax over the 16 channels (both half-warps hold identical copies)
    float m = v;
#pragma unroll
    for (int o = 8; o; o >>= 1) m = fmaxf(m, __shfl_xor_sync(0xffffffffu, m, o));
    float S = __expf(v - m);
#pragma unroll
    for (int o = 8; o; o >>= 1) S += __shfl_xor_sync(0xffffffffu, S, o);
    if (lane < 16) out[(size_t)w * OUT_CH + c] = (v - m) - __logf(S);
}

// ---------------- launch ----------------
extern "C" void kernel_launch(void* const* d_in, const int* in_sizes, int n_in,
                              void* d_out, int out_size)
{
    const float* x   = (const float*)d_in[0];
    const int*   ei  = (const int*)  d_in[1];
    const float* W1  = (const float*)d_in[2];
    const float* a1s = (const float*)d_in[3];
    const float* a1d = (const float*)d_in[4];
    const float* b1  = (const float*)d_in[5];
    const float* W2  = (const float*)d_in[6];
    const float* a2s = (const float*)d_in[7];
    const float* a2d = (const float*)d_in[8];
    const float* b2  = (const float*)d_in[9];
    float* out = (float*)d_out;

    int N      = in_sizes[0] / IN_CH;     // 100000
    int E_orig = in_sizes[1] / 2;         // 3200000
    int E_tot  = E_orig + N;

    // gemm1 kept at launch index 3 so the fixed ncu skip-count profiles it.
    k_wsplit <<<16, 256>>>(W1);
    k_zero   <<<(N + 255) / 256, 256>>>(N);
    k_deg    <<<(E_tot + 255) / 256, 256>>>(ei, E_orig, E_tot);
    k_gemm1  <<<(N + 127) / 128, 256>>>(x, a1s, a1d, N);
    k_scanA  <<<(N + 1023) / 1024, 1024>>>(N);
    k_scanB  <<<1, 1>>>((N + 1023) / 1024);
    k_scanC  <<<(N + 255) / 256, 256>>>(N);
    k_cursor <<<(N + 255) / 256, 256>>>(N);
    k_scatter<<<(E_tot + 255) / 256, 256>>>(ei, E_orig, E_tot);

    // layer 1 aggregation
    k_edge1<<<(N * 32 + 255) / 256, 256>>>(b1, N);

    // layer 2 + fused log_softmax
    k_gemm2<<<(N + 63) / 64, 256>>>(W2, a2s, a2d, N);
    k_edge2<<<(N * 32 + 255) / 256, 256>>>(b2, out, N);
}